// round 1
// baseline (speedup 1.0000x reference)
#include <cuda_runtime.h>
#include <cuda_bf16.h>
#include <math.h>

// Problem constants
#define T_LEN 2048
#define D_DIM 4096
#define NHEAD 32
#define NGRP 8
#define HDIM 128
#define KVDIM 2048   // 2 * HDIM * NGRP

// Scratch (no cudaMalloc allowed)
__device__ float g_q[T_LEN * D_DIM];     // 32 MB
__device__ float g_kv[T_LEN * KVDIM];    // 16 MB
__device__ float g_ctx[T_LEN * D_DIM];   // 32 MB

// ---------------------------------------------------------------------------
// Generic fp32 SGEMM: C[M,N] = A[M,K] @ B[K,N] (+ bias[N] if bias != null)
// 128x128 block tile, BK=16, 256 threads, 8x8 micro-tile.
// Requires M%128==0, N%128==0, K%16==0 (true for all three calls).
// ---------------------------------------------------------------------------
__global__ __launch_bounds__(256) void sgemm128(
    const float* __restrict__ A, const float* __restrict__ B,
    float* __restrict__ C, const float* __restrict__ bias,
    int M, int N, int K)
{
    __shared__ float As[16][132];   // transposed A tile [k][m], padded
    __shared__ float Bs[16][128];   // B tile [k][n]

    const int tid = threadIdx.x;
    const int bx = blockIdx.x;      // N tile
    const int by = blockIdx.y;      // M tile
    const int tx = tid & 15;        // 0..15 -> 8 cols each
    const int ty = tid >> 4;        // 0..15 -> 8 rows each

    const float* Ablk = A + (size_t)by * 128 * K;
    const float* Bblk = B + (size_t)bx * 128;

    float acc[8][8];
#pragma unroll
    for (int i = 0; i < 8; i++)
#pragma unroll
        for (int j = 0; j < 8; j++) acc[i][j] = 0.f;

    const int arow = tid >> 2;          // 0..63
    const int ac4  = (tid & 3) * 4;     // 0,4,8,12
    const int brow = tid >> 5;          // 0..7
    const int bc4  = (tid & 31) * 4;    // 0..124

    for (int k0 = 0; k0 < K; k0 += 16) {
        // Load A tile (128x16) transposed into As[k][m]
        float4 a0 = *(const float4*)(Ablk + (size_t)arow * K + k0 + ac4);
        float4 a1 = *(const float4*)(Ablk + (size_t)(arow + 64) * K + k0 + ac4);
        As[ac4 + 0][arow] = a0.x; As[ac4 + 1][arow] = a0.y;
        As[ac4 + 2][arow] = a0.z; As[ac4 + 3][arow] = a0.w;
        As[ac4 + 0][arow + 64] = a1.x; As[ac4 + 1][arow + 64] = a1.y;
        As[ac4 + 2][arow + 64] = a1.z; As[ac4 + 3][arow + 64] = a1.w;
        // Load B tile (16x128)
        *(float4*)(&Bs[brow][bc4]) =
            *(const float4*)(Bblk + (size_t)(k0 + brow) * N + bc4);
        *(float4*)(&Bs[brow + 8][bc4]) =
            *(const float4*)(Bblk + (size_t)(k0 + brow + 8) * N + bc4);
        __syncthreads();

#pragma unroll
        for (int k = 0; k < 16; k++) {
            float ar[8], br[8];
            *(float4*)(ar)     = *(const float4*)(&As[k][ty * 8]);
            *(float4*)(ar + 4) = *(const float4*)(&As[k][ty * 8 + 4]);
            *(float4*)(br)     = *(const float4*)(&Bs[k][tx * 8]);
            *(float4*)(br + 4) = *(const float4*)(&Bs[k][tx * 8 + 4]);
#pragma unroll
            for (int i = 0; i < 8; i++)
#pragma unroll
                for (int j = 0; j < 8; j++)
                    acc[i][j] = fmaf(ar[i], br[j], acc[i][j]);
        }
        __syncthreads();
    }

    // Epilogue
#pragma unroll
    for (int i = 0; i < 8; i++) {
        int row = by * 128 + ty * 8 + i;
        float* crow = C + (size_t)row * N + bx * 128 + tx * 8;
        float4 o0, o1;
        if (bias) {
            const float* bp = bias + bx * 128 + tx * 8;
            o0.x = acc[i][0] + bp[0]; o0.y = acc[i][1] + bp[1];
            o0.z = acc[i][2] + bp[2]; o0.w = acc[i][3] + bp[3];
            o1.x = acc[i][4] + bp[4]; o1.y = acc[i][5] + bp[5];
            o1.z = acc[i][6] + bp[6]; o1.w = acc[i][7] + bp[7];
        } else {
            o0.x = acc[i][0]; o0.y = acc[i][1]; o0.z = acc[i][2]; o0.w = acc[i][3];
            o1.x = acc[i][4]; o1.y = acc[i][5]; o1.z = acc[i][6]; o1.w = acc[i][7];
        }
        *(float4*)(crow)     = o0;
        *(float4*)(crow + 4) = o1;
    }
}

// ---------------------------------------------------------------------------
// Causal GQA flash attention, fp32.
// Grid: (NHEAD, T/64). Block: 256 threads = 4 d-segments x 64 query rows.
// Dynamic smem layout (floats):
//   Ksh[64][132], Vsh[64][132], Ssh[4][64][65], Psh[64][65], Ash[64]
// ---------------------------------------------------------------------------
#define KPAD 132
#define SPAD 65
#define ATT_SMEM_FLOATS (2 * 64 * KPAD + 4 * 64 * SPAD + 64 * SPAD + 64)
#define ATT_SMEM_BYTES (ATT_SMEM_FLOATS * 4)

__global__ __launch_bounds__(256) void attn_kernel(
    const float* __restrict__ q, const float* __restrict__ kv,
    float* __restrict__ ctx)
{
    const int h  = blockIdx.x;        // head 0..31
    const int qt = blockIdx.y;        // query tile 0..31
    const int g  = h >> 2;            // kv group (REP = 4)

    extern __shared__ float sm[];
    float* Ksh = sm;                          // [64][KPAD]
    float* Vsh = Ksh + 64 * KPAD;             // [64][KPAD]
    float* Ssh = Vsh + 64 * KPAD;             // [4][64][SPAD]
    float* Psh = Ssh + 4 * 64 * SPAD;         // [64][SPAD]
    float* Ash = Psh + 64 * SPAD;             // [64]

    const int tid  = threadIdx.x;
    const int qr   = tid & 63;        // query row in tile
    const int dseg = tid >> 6;        // 0..3, 32-wide d segment
    const int qg   = qt * 64 + qr;    // global query index

    // Load this thread's q slice into registers (once per block)
    float qreg[32];
    {
        const float* qp = q + (size_t)qg * D_DIM + h * HDIM + dseg * 32;
#pragma unroll
        for (int i = 0; i < 8; i++) {
            float4 v = *(const float4*)(qp + i * 4);
            qreg[i * 4 + 0] = v.x; qreg[i * 4 + 1] = v.y;
            qreg[i * 4 + 2] = v.z; qreg[i * 4 + 3] = v.w;
        }
    }

    float O[32];
#pragma unroll
    for (int d = 0; d < 32; d++) O[d] = 0.f;
    float m_run = -1e30f, l_run = 0.f;
    const float scale = 0.08838834764831845f;   // 1/sqrt(128)

    for (int kt = 0; kt <= qt; kt++) {
        // ---- Load K and V tiles (64 keys x 128) ----
        const float* kvbase = kv + (size_t)(kt * 64) * KVDIM + g * (2 * HDIM);
        for (int i = tid; i < 64 * 32; i += 256) {
            int row = i >> 5;
            int c4  = (i & 31) * 4;
            float4 kk4 = *(const float4*)(kvbase + (size_t)row * KVDIM + c4);
            float4 vv4 = *(const float4*)(kvbase + (size_t)row * KVDIM + HDIM + c4);
            *(float4*)(Ksh + row * KPAD + c4) = kk4;
            *(float4*)(Vsh + row * KPAD + c4) = vv4;
        }
        __syncthreads();

        // ---- Partial scores: dot over this thread's 32-d segment ----
        {
            float* Srow = Ssh + dseg * (64 * SPAD) + qr * SPAD;
            for (int kk = 0; kk < 64; kk++) {
                const float* kr = Ksh + kk * KPAD + dseg * 32;
                float acc = 0.f;
#pragma unroll
                for (int d4 = 0; d4 < 8; d4++) {
                    float4 kv4 = *(const float4*)(kr + d4 * 4);
                    acc = fmaf(qreg[d4 * 4 + 0], kv4.x, acc);
                    acc = fmaf(qreg[d4 * 4 + 1], kv4.y, acc);
                    acc = fmaf(qreg[d4 * 4 + 2], kv4.z, acc);
                    acc = fmaf(qreg[d4 * 4 + 3], kv4.w, acc);
                }
                Srow[kk] = acc;
            }
        }
        __syncthreads();

        // ---- Softmax (one thread per query row) ----
        if (dseg == 0) {
            float s[64];
            float mnew = m_run;
#pragma unroll
            for (int kk = 0; kk < 64; kk++) {
                float v = Ssh[0 * (64 * SPAD) + qr * SPAD + kk]
                        + Ssh[1 * (64 * SPAD) + qr * SPAD + kk]
                        + Ssh[2 * (64 * SPAD) + qr * SPAD + kk]
                        + Ssh[3 * (64 * SPAD) + qr * SPAD + kk];
                v *= scale;
                int kglob = kt * 64 + kk;
                v = (kglob <= qg) ? v : -1e30f;
                s[kk] = v;
                mnew = fmaxf(mnew, v);
            }
            float alpha = __expf(m_run - mnew);
            float psum = 0.f;
#pragma unroll
            for (int kk = 0; kk < 64; kk++) {
                float p = __expf(s[kk] - mnew);
                Psh[qr * SPAD + kk] = p;
                psum += p;
            }
            l_run = l_run * alpha + psum;
            m_run = mnew;
            Ash[qr] = alpha;
        }
        __syncthreads();

        // ---- Rescale and accumulate O += P @ V ----
        {
            float alpha = Ash[qr];
#pragma unroll
            for (int d = 0; d < 32; d++) O[d] *= alpha;
            for (int kk = 0; kk < 64; kk++) {
                float p = Psh[qr * SPAD + kk];
                const float* vr = Vsh + kk * KPAD + dseg * 32;
#pragma unroll
                for (int d4 = 0; d4 < 8; d4++) {
                    float4 v4 = *(const float4*)(vr + d4 * 4);
                    O[d4 * 4 + 0] = fmaf(p, v4.x, O[d4 * 4 + 0]);
                    O[d4 * 4 + 1] = fmaf(p, v4.y, O[d4 * 4 + 1]);
                    O[d4 * 4 + 2] = fmaf(p, v4.z, O[d4 * 4 + 2]);
                    O[d4 * 4 + 3] = fmaf(p, v4.w, O[d4 * 4 + 3]);
                }
            }
        }
        __syncthreads();
    }

    // Broadcast row sum l to all 4 d-segments
    if (dseg == 0) Ash[qr] = l_run;
    __syncthreads();
    float linv = 1.0f / Ash[qr];

    float* cp = g_ctx + (size_t)qg * D_DIM + h * HDIM + dseg * 32;
#pragma unroll
    for (int d4 = 0; d4 < 8; d4++) {
        float4 o;
        o.x = O[d4 * 4 + 0] * linv; o.y = O[d4 * 4 + 1] * linv;
        o.z = O[d4 * 4 + 2] * linv; o.w = O[d4 * 4 + 3] * linv;
        *(float4*)(cp + d4 * 4) = o;
    }
    (void)ctx;
}

// ---------------------------------------------------------------------------
// Launch
// ---------------------------------------------------------------------------
extern "C" void kernel_launch(void* const* d_in, const int* in_sizes, int n_in,
                              void* d_out, int out_size)
{
    const float* x   = (const float*)d_in[0];
    const float* Wq  = (const float*)d_in[1];
    const float* Wkv = (const float*)d_in[2];
    const float* Wo  = (const float*)d_in[3];
    const float* bo  = (const float*)d_in[4];
    float* out = (float*)d_out;

    float *qp, *kvp, *ctxp;
    cudaGetSymbolAddress((void**)&qp, g_q);
    cudaGetSymbolAddress((void**)&kvp, g_kv);
    cudaGetSymbolAddress((void**)&ctxp, g_ctx);

    cudaFuncSetAttribute(attn_kernel,
                         cudaFuncAttributeMaxDynamicSharedMemorySize,
                         ATT_SMEM_BYTES);

    // 1) q = x @ Wq    [2048,4096] = [2048,4096]@[4096,4096]
    sgemm128<<<dim3(D_DIM / 128, T_LEN / 128), 256>>>(
        x, Wq, qp, nullptr, T_LEN, D_DIM, D_DIM);

    // 2) kv = x @ Wkv  [2048,2048] = [2048,4096]@[4096,2048]
    sgemm128<<<dim3(KVDIM / 128, T_LEN / 128), 256>>>(
        x, Wkv, kvp, nullptr, T_LEN, KVDIM, D_DIM);

    // 3) causal GQA attention -> g_ctx [2048,4096]
    attn_kernel<<<dim3(NHEAD, T_LEN / 64), 256, ATT_SMEM_BYTES>>>(
        qp, kvp, ctxp);

    // 4) out = ctx @ Wo + bo
    sgemm128<<<dim3(D_DIM / 128, T_LEN / 128), 256>>>(
        ctxp, Wo, out, bo, T_LEN, D_DIM, D_DIM);

    (void)in_sizes; (void)n_in; (void)out_size;
}

// round 3
// speedup vs baseline: 1.9471x; 1.9471x over previous
#include <cuda_runtime.h>
#include <cuda_bf16.h>
#include <cstdint>
#include <math.h>

// Problem constants
#define T_LEN 2048
#define D_DIM 4096
#define NHEAD 32
#define NGRP 8
#define HDIM 128
#define KVDIM 2048   // 2 * HDIM * NGRP

// Scratch (no cudaMalloc allowed)
__device__ float g_q[T_LEN * D_DIM];       // 32 MB
__device__ float g_kv[T_LEN * KVDIM];      // 16 MB
__device__ float g_ctx[T_LEN * D_DIM];     // 32 MB

// ---------------------------------------------------------------------------
// Helpers
// ---------------------------------------------------------------------------
__device__ __forceinline__ uint32_t smem_u32(const void* p) {
    uint32_t a;
    asm("{ .reg .u64 t; cvta.to.shared.u64 t, %1; cvt.u32.u64 %0, t; }"
        : "=r"(a) : "l"(p));
    return a;
}
#define CP_ASYNC16(smem, gptr) \
    asm volatile("cp.async.cg.shared.global [%0], [%1], 16;" \
                 :: "r"(smem), "l"(gptr) : "memory")
#define CP_COMMIT() asm volatile("cp.async.commit_group;" ::: "memory")
#define CP_WAIT(N)  asm volatile("cp.async.wait_group %0;" :: "n"(N) : "memory")

__device__ __forceinline__ uint32_t f2tf32(float f) {
    uint32_t u;
    asm("cvt.rna.tf32.f32 %0, %1;" : "=r"(u) : "f"(f));
    return u;
}
__device__ __forceinline__ void mma_tf32(float* c, const uint32_t* a,
                                         const uint32_t* b) {
    asm volatile(
        "mma.sync.aligned.m16n8k8.row.col.f32.tf32.tf32.f32 "
        "{%0,%1,%2,%3}, {%4,%5,%6,%7}, {%8,%9}, {%0,%1,%2,%3};"
        : "+f"(c[0]), "+f"(c[1]), "+f"(c[2]), "+f"(c[3])
        : "r"(a[0]), "r"(a[1]), "r"(a[2]), "r"(a[3]), "r"(b[0]), "r"(b[1]));
}

// ---------------------------------------------------------------------------
// tf32 mma.sync GEMM: C[M,N] = A[M,K] @ B[K,N] (+bias)
// BM=128, BN=128, BK=16, 256 threads (8 warps, 2x4), warp tile 64x32.
// Smem: As[m][k] stride 20 floats; Bs[k][n] stride 136 floats; 2 stages.
// K = 4096 fixed.
// ---------------------------------------------------------------------------
#define GK 4096
#define NT (GK / 16)          // 256 k-tiles
#define AS_STRIDE 20          // 16 + 4 pad (80B, 16B-aligned)
#define BS_STRIDE 136         // 128 + 8 pad (544B, 16B-aligned)
#define AS_FLOATS (128 * AS_STRIDE)   // 2560
#define BS_FLOATS (16 * BS_STRIDE)    // 2176

__global__ __launch_bounds__(256, 2) void gemm_mma(
    const float* __restrict__ A, const float* __restrict__ B,
    float* __restrict__ C, const float* __restrict__ bias, int N)
{
    __shared__ float As[2][AS_FLOATS];
    __shared__ float Bs[2][BS_FLOATS];

    const int tid = threadIdx.x;
    const int wid = tid >> 5;
    const int lane = tid & 31;
    const int gid = lane >> 2;       // group id 0..7
    const int tig = lane & 3;        // thread-in-group 0..3
    const int warp_m = (wid & 1) * 64;
    const int warp_n = (wid >> 1) * 32;

    const int bx = blockIdx.x;       // N tile
    const int by = blockIdx.y;       // M tile

    const float* Ab = A + (size_t)by * 128 * GK;
    const float* Bb = B + (size_t)bx * 128;

    const uint32_t asb[2] = { smem_u32(As[0]), smem_u32(As[1]) };
    const uint32_t bsb[2] = { smem_u32(Bs[0]), smem_u32(Bs[1]) };

    // Per-thread load slots
    // A: 512 chunks of 16B (128 rows x 4): ids tid, tid+256
    const int a_r0 = tid >> 2,            a_c0 = tid & 3;
    const int a_r1 = (tid + 256) >> 2,    a_c1 = (tid + 256) & 3;
    // B: 512 chunks (16 rows x 32): ids tid, tid+256
    const int b_r0 = tid >> 5,            b_c0 = tid & 31;
    const int b_r1 = (tid + 256) >> 5,    b_c1 = (tid + 256) & 31;

    auto load_tile = [&](int kt, int s) {
        const float* ag = Ab + kt * 16;
        const float* bg = Bb + (size_t)(kt * 16) * N;
        CP_ASYNC16(asb[s] + (a_r0 * AS_STRIDE + a_c0 * 4) * 4,
                   ag + (size_t)a_r0 * GK + a_c0 * 4);
        CP_ASYNC16(asb[s] + (a_r1 * AS_STRIDE + a_c1 * 4) * 4,
                   ag + (size_t)a_r1 * GK + a_c1 * 4);
        CP_ASYNC16(bsb[s] + (b_r0 * BS_STRIDE + b_c0 * 4) * 4,
                   bg + (size_t)b_r0 * N + b_c0 * 4);
        CP_ASYNC16(bsb[s] + (b_r1 * BS_STRIDE + b_c1 * 4) * 4,
                   bg + (size_t)b_r1 * N + b_c1 * 4);
        CP_COMMIT();
    };

    float acc[4][4][4];   // [mfrag][nfrag][4]
#pragma unroll
    for (int i = 0; i < 4; i++)
#pragma unroll
        for (int j = 0; j < 4; j++)
#pragma unroll
            for (int k = 0; k < 4; k++) acc[i][j][k] = 0.f;

    load_tile(0, 0);

    for (int kt = 0; kt < NT; kt++) {
        if (kt + 1 < NT) load_tile(kt + 1, (kt + 1) & 1);
        if (kt + 1 < NT) { CP_WAIT(1); } else { CP_WAIT(0); }
        __syncthreads();

        const float* as = As[kt & 1];
        const float* bs = Bs[kt & 1];

#pragma unroll
        for (int ks = 0; ks < 2; ks++) {         // two k8 steps
            const int k0 = ks * 8;
            uint32_t afr[4][4];
#pragma unroll
            for (int mf = 0; mf < 4; mf++) {
                const float* ap = as + (warp_m + mf * 16 + gid) * AS_STRIDE + k0 + tig;
                afr[mf][0] = f2tf32(ap[0]);
                afr[mf][1] = f2tf32(ap[8 * AS_STRIDE]);
                afr[mf][2] = f2tf32(ap[4]);
                afr[mf][3] = f2tf32(ap[8 * AS_STRIDE + 4]);
            }
            uint32_t bfr[4][2];
#pragma unroll
            for (int nf = 0; nf < 4; nf++) {
                const float* bp = bs + (k0 + tig) * BS_STRIDE + warp_n + nf * 8 + gid;
                bfr[nf][0] = f2tf32(bp[0]);
                bfr[nf][1] = f2tf32(bp[4 * BS_STRIDE]);
            }
#pragma unroll
            for (int mf = 0; mf < 4; mf++)
#pragma unroll
                for (int nf = 0; nf < 4; nf++)
                    mma_tf32(acc[mf][nf], afr[mf], bfr[nf]);
        }
        __syncthreads();
    }

    // Epilogue
#pragma unroll
    for (int mf = 0; mf < 4; mf++) {
#pragma unroll
        for (int nf = 0; nf < 4; nf++) {
            int row0 = by * 128 + warp_m + mf * 16 + gid;
            int col  = bx * 128 + warp_n + nf * 8 + tig * 2;
            float b0 = 0.f, b1 = 0.f;
            if (bias) { b0 = __ldg(bias + col); b1 = __ldg(bias + col + 1); }
            float2 v0 = make_float2(acc[mf][nf][0] + b0, acc[mf][nf][1] + b1);
            float2 v1 = make_float2(acc[mf][nf][2] + b0, acc[mf][nf][3] + b1);
            *(float2*)(C + (size_t)row0 * N + col) = v0;
            *(float2*)(C + (size_t)(row0 + 8) * N + col) = v1;
        }
    }
}

// ---------------------------------------------------------------------------
// Causal GQA flash attention, fp32 SIMT (unchanged).
// ---------------------------------------------------------------------------
#define KPAD 132
#define SPAD 65
#define ATT_SMEM_FLOATS (2 * 64 * KPAD + 4 * 64 * SPAD + 64 * SPAD + 64)
#define ATT_SMEM_BYTES (ATT_SMEM_FLOATS * 4)

__global__ __launch_bounds__(256) void attn_kernel(
    const float* __restrict__ q, const float* __restrict__ kv,
    float* __restrict__ ctx)
{
    const int h  = blockIdx.x;
    const int qt = blockIdx.y;
    const int g  = h >> 2;

    extern __shared__ float smf[];
    float* Ksh = smf;
    float* Vsh = Ksh + 64 * KPAD;
    float* Ssh = Vsh + 64 * KPAD;
    float* Psh = Ssh + 4 * 64 * SPAD;
    float* Ash = Psh + 64 * SPAD;

    const int tid  = threadIdx.x;
    const int qr   = tid & 63;
    const int dseg = tid >> 6;
    const int qg   = qt * 64 + qr;

    float qreg[32];
    {
        const float* qp = q + (size_t)qg * D_DIM + h * HDIM + dseg * 32;
#pragma unroll
        for (int i = 0; i < 8; i++) {
            float4 v = *(const float4*)(qp + i * 4);
            qreg[i*4+0] = v.x; qreg[i*4+1] = v.y; qreg[i*4+2] = v.z; qreg[i*4+3] = v.w;
        }
    }

    float O[32];
#pragma unroll
    for (int d = 0; d < 32; d++) O[d] = 0.f;
    float m_run = -1e30f, l_run = 0.f;
    const float scale = 0.08838834764831845f;

    for (int kt = 0; kt <= qt; kt++) {
        const float* kvbase = kv + (size_t)(kt * 64) * KVDIM + g * (2 * HDIM);
        for (int i = tid; i < 64 * 32; i += 256) {
            int row = i >> 5;
            int c4  = (i & 31) * 4;
            float4 kk4 = *(const float4*)(kvbase + (size_t)row * KVDIM + c4);
            float4 vv4 = *(const float4*)(kvbase + (size_t)row * KVDIM + HDIM + c4);
            *(float4*)(Ksh + row * KPAD + c4) = kk4;
            *(float4*)(Vsh + row * KPAD + c4) = vv4;
        }
        __syncthreads();

        {
            float* Srow = Ssh + dseg * (64 * SPAD) + qr * SPAD;
            for (int kk = 0; kk < 64; kk++) {
                const float* kr = Ksh + kk * KPAD + dseg * 32;
                float acc = 0.f;
#pragma unroll
                for (int d4 = 0; d4 < 8; d4++) {
                    float4 kv4 = *(const float4*)(kr + d4 * 4);
                    acc = fmaf(qreg[d4*4+0], kv4.x, acc);
                    acc = fmaf(qreg[d4*4+1], kv4.y, acc);
                    acc = fmaf(qreg[d4*4+2], kv4.z, acc);
                    acc = fmaf(qreg[d4*4+3], kv4.w, acc);
                }
                Srow[kk] = acc;
            }
        }
        __syncthreads();

        if (dseg == 0) {
            float s[64];
            float mnew = m_run;
#pragma unroll
            for (int kk = 0; kk < 64; kk++) {
                float v = Ssh[0*(64*SPAD) + qr*SPAD + kk]
                        + Ssh[1*(64*SPAD) + qr*SPAD + kk]
                        + Ssh[2*(64*SPAD) + qr*SPAD + kk]
                        + Ssh[3*(64*SPAD) + qr*SPAD + kk];
                v *= scale;
                int kglob = kt * 64 + kk;
                v = (kglob <= qg) ? v : -1e30f;
                s[kk] = v;
                mnew = fmaxf(mnew, v);
            }
            float alpha = __expf(m_run - mnew);
            float psum = 0.f;
#pragma unroll
            for (int kk = 0; kk < 64; kk++) {
                float p = __expf(s[kk] - mnew);
                Psh[qr * SPAD + kk] = p;
                psum += p;
            }
            l_run = l_run * alpha + psum;
            m_run = mnew;
            Ash[qr] = alpha;
        }
        __syncthreads();

        {
            float alpha = Ash[qr];
#pragma unroll
            for (int d = 0; d < 32; d++) O[d] *= alpha;
            for (int kk = 0; kk < 64; kk++) {
                float p = Psh[qr * SPAD + kk];
                const float* vr = Vsh + kk * KPAD + dseg * 32;
#pragma unroll
                for (int d4 = 0; d4 < 8; d4++) {
                    float4 v4 = *(const float4*)(vr + d4 * 4);
                    O[d4*4+0] = fmaf(p, v4.x, O[d4*4+0]);
                    O[d4*4+1] = fmaf(p, v4.y, O[d4*4+1]);
                    O[d4*4+2] = fmaf(p, v4.z, O[d4*4+2]);
                    O[d4*4+3] = fmaf(p, v4.w, O[d4*4+3]);
                }
            }
        }
        __syncthreads();
    }

    if (dseg == 0) Ash[qr] = l_run;
    __syncthreads();
    float linv = 1.0f / Ash[qr];

    float* cp = ctx + (size_t)qg * D_DIM + h * HDIM + dseg * 32;
#pragma unroll
    for (int d4 = 0; d4 < 8; d4++) {
        float4 o;
        o.x = O[d4*4+0] * linv; o.y = O[d4*4+1] * linv;
        o.z = O[d4*4+2] * linv; o.w = O[d4*4+3] * linv;
        *(float4*)(cp + d4 * 4) = o;
    }
}

// ---------------------------------------------------------------------------
// Launch
// ---------------------------------------------------------------------------
extern "C" void kernel_launch(void* const* d_in, const int* in_sizes, int n_in,
                              void* d_out, int out_size)
{
    const float* x   = (const float*)d_in[0];
    const float* Wq  = (const float*)d_in[1];
    const float* Wkv = (const float*)d_in[2];
    const float* Wo  = (const float*)d_in[3];
    const float* bo  = (const float*)d_in[4];
    float* out = (float*)d_out;

    float *qp, *kvp, *ctxp;
    cudaGetSymbolAddress((void**)&qp,  g_q);
    cudaGetSymbolAddress((void**)&kvp, g_kv);
    cudaGetSymbolAddress((void**)&ctxp, g_ctx);

    cudaFuncSetAttribute(attn_kernel,
                         cudaFuncAttributeMaxDynamicSharedMemorySize,
                         ATT_SMEM_BYTES);

    // 1) q = x @ Wq   [2048,4096]
    gemm_mma<<<dim3(D_DIM / 128, T_LEN / 128), 256>>>(x, Wq, qp, nullptr, D_DIM);
    // 2) kv = x @ Wkv [2048,2048]
    gemm_mma<<<dim3(KVDIM / 128, T_LEN / 128), 256>>>(x, Wkv, kvp, nullptr, KVDIM);
    // 3) attention
    attn_kernel<<<dim3(NHEAD, T_LEN / 64), 256, ATT_SMEM_BYTES>>>(qp, kvp, ctxp);
    // 4) out = ctx @ Wo + bo
    gemm_mma<<<dim3(D_DIM / 128, T_LEN / 128), 256>>>(ctxp, Wo, out, bo, D_DIM);

    (void)in_sizes; (void)n_in; (void)out_size;
}

// round 4
// speedup vs baseline: 3.5582x; 1.8274x over previous
#include <cuda_runtime.h>
#include <cuda_bf16.h>
#include <cstdint>
#include <math.h>

// Problem constants
#define T_LEN 2048
#define D_DIM 4096
#define NHEAD 32
#define NGRP 8
#define HDIM 128
#define KVDIM 2048   // 2 * HDIM * NGRP

// Scratch (no cudaMalloc allowed)
__device__ float g_q[T_LEN * D_DIM];       // 32 MB
__device__ float g_kv[T_LEN * KVDIM];      // 16 MB
__device__ float g_ctx[T_LEN * D_DIM];     // 32 MB

// ---------------------------------------------------------------------------
// Helpers
// ---------------------------------------------------------------------------
__device__ __forceinline__ uint32_t smem_u32(const void* p) {
    uint32_t a;
    asm("{ .reg .u64 t; cvta.to.shared.u64 t, %1; cvt.u32.u64 %0, t; }"
        : "=r"(a) : "l"(p));
    return a;
}
#define CP_ASYNC16(smem, gptr) \
    asm volatile("cp.async.cg.shared.global [%0], [%1], 16;" \
                 :: "r"(smem), "l"(gptr) : "memory")
#define CP_COMMIT() asm volatile("cp.async.commit_group;" ::: "memory")
#define CP_WAIT(N)  asm volatile("cp.async.wait_group %0;" :: "n"(N) : "memory")

__device__ __forceinline__ uint32_t f2tf32(float f) {
    uint32_t u;
    asm("cvt.rna.tf32.f32 %0, %1;" : "=r"(u) : "f"(f));
    return u;
}
__device__ __forceinline__ void mma_tf32(float* c, const uint32_t* a,
                                         const uint32_t* b) {
    asm volatile(
        "mma.sync.aligned.m16n8k8.row.col.f32.tf32.tf32.f32 "
        "{%0,%1,%2,%3}, {%4,%5,%6,%7}, {%8,%9}, {%0,%1,%2,%3};"
        : "+f"(c[0]), "+f"(c[1]), "+f"(c[2]), "+f"(c[3])
        : "r"(a[0]), "r"(a[1]), "r"(a[2]), "r"(a[3]), "r"(b[0]), "r"(b[1]));
}

// ---------------------------------------------------------------------------
// tf32 mma.sync GEMM (unchanged from round 3)
// ---------------------------------------------------------------------------
#define GK 4096
#define NT (GK / 16)
#define AS_STRIDE 20
#define BS_STRIDE 136
#define AS_FLOATS (128 * AS_STRIDE)
#define BS_FLOATS (16 * BS_STRIDE)

__global__ __launch_bounds__(256, 2) void gemm_mma(
    const float* __restrict__ A, const float* __restrict__ B,
    float* __restrict__ C, const float* __restrict__ bias, int N)
{
    __shared__ float As[2][AS_FLOATS];
    __shared__ float Bs[2][BS_FLOATS];

    const int tid = threadIdx.x;
    const int wid = tid >> 5;
    const int lane = tid & 31;
    const int gid = lane >> 2;
    const int tig = lane & 3;
    const int warp_m = (wid & 1) * 64;
    const int warp_n = (wid >> 1) * 32;

    const int bx = blockIdx.x;
    const int by = blockIdx.y;

    const float* Ab = A + (size_t)by * 128 * GK;
    const float* Bb = B + (size_t)bx * 128;

    const uint32_t asb[2] = { smem_u32(As[0]), smem_u32(As[1]) };
    const uint32_t bsb[2] = { smem_u32(Bs[0]), smem_u32(Bs[1]) };

    const int a_r0 = tid >> 2,         a_c0 = tid & 3;
    const int a_r1 = (tid + 256) >> 2, a_c1 = (tid + 256) & 3;
    const int b_r0 = tid >> 5,         b_c0 = tid & 31;
    const int b_r1 = (tid + 256) >> 5, b_c1 = (tid + 256) & 31;

    auto load_tile = [&](int kt, int s) {
        const float* ag = Ab + kt * 16;
        const float* bg = Bb + (size_t)(kt * 16) * N;
        CP_ASYNC16(asb[s] + (a_r0 * AS_STRIDE + a_c0 * 4) * 4,
                   ag + (size_t)a_r0 * GK + a_c0 * 4);
        CP_ASYNC16(asb[s] + (a_r1 * AS_STRIDE + a_c1 * 4) * 4,
                   ag + (size_t)a_r1 * GK + a_c1 * 4);
        CP_ASYNC16(bsb[s] + (b_r0 * BS_STRIDE + b_c0 * 4) * 4,
                   bg + (size_t)b_r0 * N + b_c0 * 4);
        CP_ASYNC16(bsb[s] + (b_r1 * BS_STRIDE + b_c1 * 4) * 4,
                   bg + (size_t)b_r1 * N + b_c1 * 4);
        CP_COMMIT();
    };

    float acc[4][4][4];
#pragma unroll
    for (int i = 0; i < 4; i++)
#pragma unroll
        for (int j = 0; j < 4; j++)
#pragma unroll
            for (int k = 0; k < 4; k++) acc[i][j][k] = 0.f;

    load_tile(0, 0);

    for (int kt = 0; kt < NT; kt++) {
        if (kt + 1 < NT) load_tile(kt + 1, (kt + 1) & 1);
        if (kt + 1 < NT) { CP_WAIT(1); } else { CP_WAIT(0); }
        __syncthreads();

        const float* as = As[kt & 1];
        const float* bs = Bs[kt & 1];

#pragma unroll
        for (int ks = 0; ks < 2; ks++) {
            const int k0 = ks * 8;
            uint32_t afr[4][4];
#pragma unroll
            for (int mf = 0; mf < 4; mf++) {
                const float* ap = as + (warp_m + mf * 16 + gid) * AS_STRIDE + k0 + tig;
                afr[mf][0] = f2tf32(ap[0]);
                afr[mf][1] = f2tf32(ap[8 * AS_STRIDE]);
                afr[mf][2] = f2tf32(ap[4]);
                afr[mf][3] = f2tf32(ap[8 * AS_STRIDE + 4]);
            }
            uint32_t bfr[4][2];
#pragma unroll
            for (int nf = 0; nf < 4; nf++) {
                const float* bp = bs + (k0 + tig) * BS_STRIDE + warp_n + nf * 8 + gid;
                bfr[nf][0] = f2tf32(bp[0]);
                bfr[nf][1] = f2tf32(bp[4 * BS_STRIDE]);
            }
#pragma unroll
            for (int mf = 0; mf < 4; mf++)
#pragma unroll
                for (int nf = 0; nf < 4; nf++)
                    mma_tf32(acc[mf][nf], afr[mf], bfr[nf]);
        }
        __syncthreads();
    }

#pragma unroll
    for (int mf = 0; mf < 4; mf++) {
#pragma unroll
        for (int nf = 0; nf < 4; nf++) {
            int row0 = by * 128 + warp_m + mf * 16 + gid;
            int col  = bx * 128 + warp_n + nf * 8 + tig * 2;
            float b0 = 0.f, b1 = 0.f;
            if (bias) { b0 = __ldg(bias + col); b1 = __ldg(bias + col + 1); }
            float2 v0 = make_float2(acc[mf][nf][0] + b0, acc[mf][nf][1] + b1);
            float2 v1 = make_float2(acc[mf][nf][2] + b0, acc[mf][nf][3] + b1);
            *(float2*)(C + (size_t)row0 * N + col) = v0;
            *(float2*)(C + (size_t)(row0 + 8) * N + col) = v1;
        }
    }
}

// ---------------------------------------------------------------------------
// Tensor-core causal GQA flash attention (tf32 mma.sync).
// Grid (NHEAD, T/64). Block 128 threads = 4 warps x 16 query rows.
// Smem (uint32, tf32-converted at store): Ksh[64][132], Vsh[64][136],
//   Psh[4][16][68].
// ---------------------------------------------------------------------------
#define AKPAD 132
#define AVPAD 136
#define APPAD 68
#define ATT_SMEM_UINTS (64 * AKPAD + 64 * AVPAD + 4 * 16 * APPAD)
#define ATT_SMEM_BYTES (ATT_SMEM_UINTS * 4)

__global__ __launch_bounds__(128, 2) void attn_mma(
    const float* __restrict__ q, const float* __restrict__ kv,
    float* __restrict__ ctx)
{
    const int h  = blockIdx.x;
    const int qt = blockIdx.y;
    const int g  = h >> 2;

    extern __shared__ uint32_t smu[];
    uint32_t* Ksh = smu;                       // [64][AKPAD]
    uint32_t* Vsh = Ksh + 64 * AKPAD;          // [64][AVPAD]
    uint32_t* Psh = Vsh + 64 * AVPAD;          // [4][16][APPAD]

    const int tid  = threadIdx.x;
    const int wid  = tid >> 5;
    const int lane = tid & 31;
    const int gid  = lane >> 2;
    const int tig  = lane & 3;

    uint32_t* Pw = Psh + wid * 16 * APPAD;

    const int r0 = qt * 64 + wid * 16;         // warp's first query row
    const int rowg0 = r0 + gid;
    const int rowg1 = r0 + gid + 8;

    // Q fragments (tf32), loaded once
    uint32_t qf[16][4];
    {
        const float* qb = q + (size_t)rowg0 * D_DIM + h * HDIM;
#pragma unroll
        for (int kf = 0; kf < 16; kf++) {
            int c = kf * 8 + tig;
            qf[kf][0] = f2tf32(qb[c]);
            qf[kf][1] = f2tf32(qb[8 * D_DIM + c]);
            qf[kf][2] = f2tf32(qb[c + 4]);
            qf[kf][3] = f2tf32(qb[8 * D_DIM + c + 4]);
        }
    }

    float o[16][4];
#pragma unroll
    for (int nf = 0; nf < 16; nf++)
#pragma unroll
        for (int j = 0; j < 4; j++) o[nf][j] = 0.f;
    float m0 = -1e30f, m1 = -1e30f, l0 = 0.f, l1 = 0.f;
    const float scale = 0.08838834764831845f;

    for (int kt = 0; kt <= qt; kt++) {
        __syncthreads();   // all warps done with previous K/V
        // Cooperative load + tf32 convert of K,V tiles (64 keys x 128)
        const float* kvb = kv + (size_t)(kt * 64) * KVDIM + g * (2 * HDIM);
        for (int i = tid; i < 64 * 32; i += 128) {
            int row = i >> 5;
            int c4  = (i & 31) * 4;
            float4 kk = *(const float4*)(kvb + (size_t)row * KVDIM + c4);
            float4 vv = *(const float4*)(kvb + (size_t)row * KVDIM + HDIM + c4);
            uint32_t* kp = Ksh + row * AKPAD + c4;
            kp[0] = f2tf32(kk.x); kp[1] = f2tf32(kk.y);
            kp[2] = f2tf32(kk.z); kp[3] = f2tf32(kk.w);
            uint32_t* vp = Vsh + row * AVPAD + c4;
            vp[0] = f2tf32(vv.x); vp[1] = f2tf32(vv.y);
            vp[2] = f2tf32(vv.z); vp[3] = f2tf32(vv.w);
        }
        __syncthreads();

        // ---- S = Q @ K^T  (16 x 64 per warp) ----
        float sa[8][4];
#pragma unroll
        for (int nf = 0; nf < 8; nf++)
#pragma unroll
            for (int j = 0; j < 4; j++) sa[nf][j] = 0.f;

#pragma unroll
        for (int kf = 0; kf < 16; kf++) {
#pragma unroll
            for (int nf = 0; nf < 8; nf++) {
                const uint32_t* kp = Ksh + (nf * 8 + gid) * AKPAD + kf * 8 + tig;
                uint32_t bfr[2] = { kp[0], kp[4] };
                mma_tf32(sa[nf], qf[kf], bfr);
            }
        }

        // ---- scale + causal mask ----
        const bool diag = (kt == qt);
#pragma unroll
        for (int nf = 0; nf < 8; nf++) {
            int c = kt * 64 + nf * 8 + 2 * tig;
#pragma unroll
            for (int j = 0; j < 4; j++) sa[nf][j] *= scale;
            if (diag) {
                if (c     > rowg0) sa[nf][0] = -1e30f;
                if (c + 1 > rowg0) sa[nf][1] = -1e30f;
                if (c     > rowg1) sa[nf][2] = -1e30f;
                if (c + 1 > rowg1) sa[nf][3] = -1e30f;
            }
        }

        // ---- row max (reduce over tig lanes) ----
        float mx0 = -1e30f, mx1 = -1e30f;
#pragma unroll
        for (int nf = 0; nf < 8; nf++) {
            mx0 = fmaxf(mx0, fmaxf(sa[nf][0], sa[nf][1]));
            mx1 = fmaxf(mx1, fmaxf(sa[nf][2], sa[nf][3]));
        }
        mx0 = fmaxf(mx0, __shfl_xor_sync(0xffffffff, mx0, 1));
        mx0 = fmaxf(mx0, __shfl_xor_sync(0xffffffff, mx0, 2));
        mx1 = fmaxf(mx1, __shfl_xor_sync(0xffffffff, mx1, 1));
        mx1 = fmaxf(mx1, __shfl_xor_sync(0xffffffff, mx1, 2));

        float mn0 = fmaxf(m0, mx0), mn1 = fmaxf(m1, mx1);
        float al0 = __expf(m0 - mn0), al1 = __expf(m1 - mn1);

        // ---- exp, P to smem (tf32), row sum ----
        float s0 = 0.f, s1 = 0.f;
#pragma unroll
        for (int nf = 0; nf < 8; nf++) {
            float p00 = __expf(sa[nf][0] - mn0);
            float p01 = __expf(sa[nf][1] - mn0);
            float p10 = __expf(sa[nf][2] - mn1);
            float p11 = __expf(sa[nf][3] - mn1);
            s0 += p00 + p01;
            s1 += p10 + p11;
            uint32_t* pp0 = Pw + gid * APPAD + nf * 8 + 2 * tig;
            pp0[0] = f2tf32(p00); pp0[1] = f2tf32(p01);
            uint32_t* pp1 = Pw + (gid + 8) * APPAD + nf * 8 + 2 * tig;
            pp1[0] = f2tf32(p10); pp1[1] = f2tf32(p11);
        }
        s0 += __shfl_xor_sync(0xffffffff, s0, 1);
        s0 += __shfl_xor_sync(0xffffffff, s0, 2);
        s1 += __shfl_xor_sync(0xffffffff, s1, 1);
        s1 += __shfl_xor_sync(0xffffffff, s1, 2);

        l0 = l0 * al0 + s0;
        l1 = l1 * al1 + s1;
        m0 = mn0; m1 = mn1;

        // ---- rescale O ----
#pragma unroll
        for (int nf = 0; nf < 16; nf++) {
            o[nf][0] *= al0; o[nf][1] *= al0;
            o[nf][2] *= al1; o[nf][3] *= al1;
        }
        __syncwarp();

        // ---- O += P @ V ----
#pragma unroll
        for (int kf = 0; kf < 8; kf++) {
            uint32_t pa[4];
            pa[0] = Pw[gid * APPAD + kf * 8 + tig];
            pa[1] = Pw[(gid + 8) * APPAD + kf * 8 + tig];
            pa[2] = Pw[gid * APPAD + kf * 8 + tig + 4];
            pa[3] = Pw[(gid + 8) * APPAD + kf * 8 + tig + 4];
#pragma unroll
            for (int nf = 0; nf < 16; nf++) {
                const uint32_t* vp = Vsh + (kf * 8 + tig) * AVPAD + nf * 8 + gid;
                uint32_t bfr[2] = { vp[0], vp[4 * AVPAD] };
                mma_tf32(o[nf], pa, bfr);
            }
        }
        __syncwarp();
    }

    // ---- normalize + write ----
    float inv0 = 1.0f / l0, inv1 = 1.0f / l1;
    float* cb = ctx + (size_t)rowg0 * D_DIM + h * HDIM;
#pragma unroll
    for (int nf = 0; nf < 16; nf++) {
        int c = nf * 8 + 2 * tig;
        *(float2*)(cb + c) = make_float2(o[nf][0] * inv0, o[nf][1] * inv0);
        *(float2*)(cb + 8 * D_DIM + c) = make_float2(o[nf][2] * inv1, o[nf][3] * inv1);
    }
}

// ---------------------------------------------------------------------------
// Launch
// ---------------------------------------------------------------------------
extern "C" void kernel_launch(void* const* d_in, const int* in_sizes, int n_in,
                              void* d_out, int out_size)
{
    const float* x   = (const float*)d_in[0];
    const float* Wq  = (const float*)d_in[1];
    const float* Wkv = (const float*)d_in[2];
    const float* Wo  = (const float*)d_in[3];
    const float* bo  = (const float*)d_in[4];
    float* out = (float*)d_out;

    float *qp, *kvp, *ctxp;
    cudaGetSymbolAddress((void**)&qp,  g_q);
    cudaGetSymbolAddress((void**)&kvp, g_kv);
    cudaGetSymbolAddress((void**)&ctxp, g_ctx);

    cudaFuncSetAttribute(attn_mma,
                         cudaFuncAttributeMaxDynamicSharedMemorySize,
                         ATT_SMEM_BYTES);

    // 1) q = x @ Wq
    gemm_mma<<<dim3(D_DIM / 128, T_LEN / 128), 256>>>(x, Wq, qp, nullptr, D_DIM);
    // 2) kv = x @ Wkv
    gemm_mma<<<dim3(KVDIM / 128, T_LEN / 128), 256>>>(x, Wkv, kvp, nullptr, KVDIM);
    // 3) attention (tensor core)
    attn_mma<<<dim3(NHEAD, T_LEN / 64), 128, ATT_SMEM_BYTES>>>(qp, kvp, ctxp);
    // 4) out = ctx @ Wo + bo
    gemm_mma<<<dim3(D_DIM / 128, T_LEN / 128), 256>>>(ctxp, Wo, out, bo, D_DIM);

    (void)in_sizes; (void)n_in; (void)out_size;
}